// round 2
// baseline (speedup 1.0000x reference)
#include <cuda_runtime.h>
#include <cuda_bf16.h>
#include <math.h>

#define T_TOK 2048
#define D_HID 1024
#define FF    512
#define NE    16
#define TOPK  4
#define CL    3
#define EPS   1e-5f
#define TK    (T_TOK*TOPK)

// ---------------- scratch (static device globals; no runtime alloc) ----------
__device__ float g_h1 [T_TOK*D_HID];
__device__ float g_res1[T_TOK*D_HID];
__device__ float g_bcx[T_TOK*3*D_HID];
__device__ float g_ypre[T_TOK*D_HID];
__device__ float g_y  [T_TOK*D_HID];
__device__ float g_h2 [T_TOK*D_HID];
__device__ float g_gu [TK*2*FF];
__device__ float g_act[TK*FF];
__device__ float g_ye [TK*D_HID];
__device__ int   g_topi[TK];
__device__ float g_topw[TK];
__device__ int   g_counts[NE];
__device__ int   g_offsets[NE];
__device__ int   g_fill[NE];
__device__ int   g_rowtok[TK];
__device__ int   g_slot[TK];

// ---------------- fused add + rmsnorm ----------------------------------------
__global__ void norm_kernel(const float* __restrict__ x, const float* __restrict__ rin,
                            const float* __restrict__ w, float* __restrict__ hout,
                            float* __restrict__ rout) {
    int t = blockIdx.x;
    int base = threadIdx.x * 4;
    size_t off = (size_t)t * D_HID + base;
    float4 xv = *(const float4*)(x + off);
    float4 rv = *(const float4*)(rin + off);
    float4 s;
    s.x = xv.x + rv.x; s.y = xv.y + rv.y; s.z = xv.z + rv.z; s.w = xv.w + rv.w;
    *(float4*)(rout + off) = s;
    float ss = s.x*s.x + s.y*s.y + s.z*s.z + s.w*s.w;
    #pragma unroll
    for (int o = 16; o > 0; o >>= 1) ss += __shfl_down_sync(0xffffffffu, ss, o);
    __shared__ float sm[8];
    __shared__ float s_inv;
    if ((threadIdx.x & 31) == 0) sm[threadIdx.x >> 5] = ss;
    __syncthreads();
    if (threadIdx.x == 0) {
        float tot = 0.f;
        #pragma unroll
        for (int i = 0; i < 8; i++) tot += sm[i];
        s_inv = rsqrtf(tot / (float)D_HID + EPS);
    }
    __syncthreads();
    float inv = s_inv;
    float4 wv = *(const float4*)(w + base);
    float4 o;
    o.x = s.x*inv*wv.x; o.y = s.y*inv*wv.y; o.z = s.z*inv*wv.z; o.w = s.w*inv*wv.w;
    *(float4*)(hout + off) = o;
}

// ---------------- tiled SGEMM: C[m,n] = sum_k A[m,k]*B[n,k] ------------------
// MODE 0: plain. MODE 1: grouped, A-rows gathered via g_rowtok (MoE gemm1).
// MODE 2: grouped, compact A rows (MoE gemm2).
template<int MODE>
__global__ __launch_bounds__(256, 2)
void sgemm_tile(const float* __restrict__ Aall, const float* __restrict__ Ball,
                float* __restrict__ Call, int Mtot, int N, int K) {
    __shared__ float As[8][128];
    __shared__ float Bs[8][128];

    int cnt = Mtot, base = 0;
    const float* Bp = Ball;
    if (MODE > 0) {
        int e = blockIdx.z;
        cnt  = g_counts[e];
        base = g_offsets[e];
        Bp   = Ball + (size_t)e * ((MODE == 1) ? (2*FF*D_HID) : (D_HID*FF));
    }
    int m0 = blockIdx.y * 128;
    if (m0 >= cnt) return;
    int n0 = blockIdx.x * 128;

    int tid = threadIdx.x;
    int lr = tid >> 1;
    int lc = (tid & 1) * 4;

    const float* arow;
    bool avalid = true;
    if (MODE == 0) {
        arow = Aall + (size_t)(m0 + lr) * K;
    } else if (MODE == 1) {
        int r = m0 + lr;
        avalid = (r < cnt);
        int tok = avalid ? g_rowtok[base + r] : 0;
        arow = Aall + (size_t)tok * K;
    } else {
        int r = m0 + lr;
        avalid = (r < cnt);
        arow = Aall + (size_t)(base + (avalid ? r : 0)) * K;
    }
    const float* brow = Bp + (size_t)(n0 + lr) * K;

    int tx = tid & 15, ty = tid >> 4;
    float acc[8][8];
    #pragma unroll
    for (int i = 0; i < 8; i++)
        #pragma unroll
        for (int j = 0; j < 8; j++) acc[i][j] = 0.f;

    for (int k0 = 0; k0 < K; k0 += 8) {
        float4 av = avalid ? *(const float4*)(arow + k0 + lc) : make_float4(0.f,0.f,0.f,0.f);
        float4 bv = *(const float4*)(brow + k0 + lc);
        __syncthreads();
        As[lc+0][lr] = av.x; As[lc+1][lr] = av.y; As[lc+2][lr] = av.z; As[lc+3][lr] = av.w;
        Bs[lc+0][lr] = bv.x; Bs[lc+1][lr] = bv.y; Bs[lc+2][lr] = bv.z; Bs[lc+3][lr] = bv.w;
        __syncthreads();
        #pragma unroll
        for (int kk = 0; kk < 8; kk++) {
            float4 a0 = *(const float4*)&As[kk][ty*4];
            float4 a1 = *(const float4*)&As[kk][64 + ty*4];
            float4 b0 = *(const float4*)&Bs[kk][tx*4];
            float4 b1 = *(const float4*)&Bs[kk][64 + tx*4];
            float a[8] = {a0.x,a0.y,a0.z,a0.w,a1.x,a1.y,a1.z,a1.w};
            float b[8] = {b0.x,b0.y,b0.z,b0.w,b1.x,b1.y,b1.z,b1.w};
            #pragma unroll
            for (int i = 0; i < 8; i++)
                #pragma unroll
                for (int j = 0; j < 8; j++)
                    acc[i][j] += a[i] * b[j];
        }
    }

    #pragma unroll
    for (int i = 0; i < 8; i++) {
        int lrr = (i < 4) ? (ty*4 + i) : (64 + ty*4 + i - 4);
        int m = m0 + lrr;
        if (MODE != 0 && m >= cnt) continue;
        size_t crow = (size_t)((MODE == 0) ? m : (base + m)) * N + n0;
        float4 v0 = make_float4(acc[i][0], acc[i][1], acc[i][2], acc[i][3]);
        float4 v1 = make_float4(acc[i][4], acc[i][5], acc[i][6], acc[i][7]);
        *(float4*)(Call + crow + tx*4)      = v0;
        *(float4*)(Call + crow + 64 + tx*4) = v1;
    }
}

// ---------------- short conv (causal depthwise, L=3) + C-gate -----------------
__global__ void conv_kernel(const float* __restrict__ convw) {
    int i = blockIdx.x * blockDim.x + threadIdx.x;
    if (i >= T_TOK * D_HID) return;
    int t = i / D_HID, d = i % D_HID;
    float w0 = convw[d*CL + 0], w1 = convw[d*CL + 1], w2 = convw[d*CL + 2];
    const float* bc = g_bcx;
    size_t r0 = (size_t)t * 3 * D_HID;
    float acc = w2 * bc[r0 + d] * bc[r0 + 2*D_HID + d];
    if (t >= 1) { size_t r1 = r0 - 3*D_HID; acc += w1 * bc[r1 + d] * bc[r1 + 2*D_HID + d]; }
    if (t >= 2) { size_t r2 = r0 - 6*D_HID; acc += w0 * bc[r2 + d] * bc[r2 + 2*D_HID + d]; }
    g_ypre[i] = bc[r0 + D_HID + d] * acc;
}

// ---------------- gating: sigmoid scores, biased top-4, renorm ---------------
__global__ void zero_counts_kernel() {
    if (threadIdx.x < NE) g_counts[threadIdx.x] = 0;
}

__global__ void gate_kernel(const float* __restrict__ h2, const float* __restrict__ gw,
                            const float* __restrict__ gb) {
    int t = blockIdx.x;
    int warp = threadIdx.x >> 5, lane = threadIdx.x & 31;
    const float* hr = h2 + (size_t)t * D_HID;
    const float* wr = gw + (size_t)warp * D_HID;
    float p = 0.f;
    for (int k = lane; k < D_HID; k += 32) p += hr[k] * wr[k];
    #pragma unroll
    for (int o = 16; o > 0; o >>= 1) p += __shfl_down_sync(0xffffffffu, p, o);
    __shared__ float s_logit[NE];
    if (lane == 0) s_logit[warp] = p;
    __syncthreads();
    if (threadIdx.x == 0) {
        float sc[NE], ch[NE];
        bool used[NE];
        #pragma unroll
        for (int e = 0; e < NE; e++) {
            float s = 1.f / (1.f + expf(-s_logit[e]));
            sc[e] = s; ch[e] = s + gb[e]; used[e] = false;
        }
        int idx[TOPK]; float wsum = 0.f;
        #pragma unroll
        for (int k = 0; k < TOPK; k++) {
            float best = -1e30f; int bi = 0;
            #pragma unroll
            for (int e = 0; e < NE; e++)
                if (!used[e] && ch[e] > best) { best = ch[e]; bi = e; }
            used[bi] = true; idx[k] = bi; wsum += sc[bi];
        }
        float inv = 1.f / (wsum + 1e-20f);
        #pragma unroll
        for (int k = 0; k < TOPK; k++) {
            g_topi[t*TOPK + k] = idx[k];
            g_topw[t*TOPK + k] = sc[idx[k]] * inv;
            atomicAdd(&g_counts[idx[k]], 1);
        }
    }
}

__global__ void scan_kernel() {
    if (threadIdx.x == 0) {
        int acc = 0;
        for (int e = 0; e < NE; e++) { g_offsets[e] = acc; acc += g_counts[e]; }
    }
    if (threadIdx.x < NE) g_fill[threadIdx.x] = 0;
}

__global__ void fill_kernel() {
    int i = blockIdx.x * blockDim.x + threadIdx.x;
    if (i >= TK) return;
    int e = g_topi[i];
    int pos = g_offsets[e] + atomicAdd(&g_fill[e], 1);
    g_rowtok[pos] = i / TOPK;
    g_slot[i] = pos;
}

// ---------------- SiLU(g) * u --------------------------------------------------
__global__ void act_kernel() {
    int i = blockIdx.x * blockDim.x + threadIdx.x;
    if (i >= TK * FF) return;
    int r = i / FF, f = i % FF;
    float g = g_gu[(size_t)r * (2*FF) + f];
    float u = g_gu[(size_t)r * (2*FF) + FF + f];
    g_act[i] = (g / (1.f + expf(-g))) * u;
}

// ---------------- combine: out[t,d] = sum_k w_k * ye[slot(t,k), d] ------------
__global__ void combine_kernel(float* __restrict__ out) {
    int i = blockIdx.x * blockDim.x + threadIdx.x;
    if (i >= T_TOK * D_HID) return;
    int t = i / D_HID, d = i % D_HID;
    float s = 0.f;
    #pragma unroll
    for (int k = 0; k < TOPK; k++)
        s += g_topw[t*TOPK + k] * g_ye[(size_t)g_slot[t*TOPK + k] * D_HID + d];
    out[i] = s;   // SCALE = 1.0
}

// ---------------- launch -------------------------------------------------------
extern "C" void kernel_launch(void* const* d_in, const int* in_sizes, int n_in,
                              void* d_out, int out_size) {
    const float* hs    = (const float*)d_in[0];
    const float* res   = (const float*)d_in[1];
    const float* opw   = (const float*)d_in[2];
    const float* ffnw  = (const float*)d_in[3];
    const float* inw   = (const float*)d_in[4];
    const float* convw = (const float*)d_in[5];
    const float* outw  = (const float*)d_in[6];
    const float* gw    = (const float*)d_in[7];
    const float* gb    = (const float*)d_in[8];
    const float* w1    = (const float*)d_in[9];
    const float* w2    = (const float*)d_in[10];
    float* out = (float*)d_out;
    float* res_out = out + (size_t)T_TOK * D_HID;

    float *p_h1, *p_res1, *p_bcx, *p_ypre, *p_y, *p_h2, *p_gu, *p_act, *p_ye;
    cudaGetSymbolAddress((void**)&p_h1,   g_h1);
    cudaGetSymbolAddress((void**)&p_res1, g_res1);
    cudaGetSymbolAddress((void**)&p_bcx,  g_bcx);
    cudaGetSymbolAddress((void**)&p_ypre, g_ypre);
    cudaGetSymbolAddress((void**)&p_y,    g_y);
    cudaGetSymbolAddress((void**)&p_h2,   g_h2);
    cudaGetSymbolAddress((void**)&p_gu,   g_gu);
    cudaGetSymbolAddress((void**)&p_act,  g_act);
    cudaGetSymbolAddress((void**)&p_ye,   g_ye);

    // 1) h1 = rmsnorm(hs + res); res1 = hs + res
    norm_kernel<<<T_TOK, 256>>>(hs, res, opw, p_h1, p_res1);

    // 2) bcx = h1 @ in_proj^T   [2048 x 3072]
    sgemm_tile<0><<<dim3(3*D_HID/128, T_TOK/128, 1), 256>>>(p_h1, inw, p_bcx, T_TOK, 3*D_HID, D_HID);

    // 3) short conv + C gate -> ypre
    conv_kernel<<<(T_TOK*D_HID + 255)/256, 256>>>(convw);

    // 4) y = ypre @ out_proj^T  [2048 x 1024]
    sgemm_tile<0><<<dim3(D_HID/128, T_TOK/128, 1), 256>>>(p_ypre, outw, p_y, T_TOK, D_HID, D_HID);

    // 5) h2 = rmsnorm(y + res1); residual out = y + res1
    norm_kernel<<<T_TOK, 256>>>(p_y, p_res1, ffnw, p_h2, res_out);

    // 6-9) gating + bucketing
    zero_counts_kernel<<<1, 32>>>();
    gate_kernel<<<T_TOK, NE*32>>>(p_h2, gw, gb);
    scan_kernel<<<1, 32>>>();
    fill_kernel<<<(TK + 255)/256, 256>>>();

    // 10) gu = gather(h2) @ w1[e]^T   (grouped)
    sgemm_tile<1><<<dim3(2*FF/128, T_TOK/128, NE), 256>>>(p_h2, w1, p_gu, T_TOK, 2*FF, D_HID);

    // 11) act = silu(g) * u
    act_kernel<<<(TK*FF + 255)/256, 256>>>();

    // 12) ye = act @ w2[e]^T (grouped), then combine
    sgemm_tile<2><<<dim3(D_HID/128, T_TOK/128, NE), 256>>>(p_act, w2, p_ye, T_TOK, D_HID, FF);
    combine_kernel<<<(T_TOK*D_HID + 255)/256, 256>>>(out);
}

// round 4
// speedup vs baseline: 2.3089x; 2.3089x over previous
#include <cuda_runtime.h>
#include <cuda_bf16.h>
#include <math.h>
#include <stdint.h>

#define T_TOK 2048
#define D_HID 1024
#define FF    512
#define NE    16
#define TOPK  4
#define CL    3
#define EPS   1e-5f
#define TK    (T_TOK*TOPK)

// ---------------- fp32 scratch ------------------------------------------------
__device__ float g_h1  [T_TOK*D_HID];
__device__ float g_res1[T_TOK*D_HID];
__device__ float g_bcx [T_TOK*3*D_HID];
__device__ float g_y   [T_TOK*D_HID];
__device__ float g_h2  [T_TOK*D_HID];
__device__ float g_gu  [TK*2*FF];
__device__ float g_ye  [TK*D_HID];
__device__ int   g_topi[TK];
__device__ float g_topw[TK];
__device__ int   g_counts[NE];
__device__ int   g_offsets[NE];
__device__ int   g_fill[NE];
__device__ int   g_rowtok[TK];
__device__ int   g_slot[TK];

// ---------------- bf16 hi/lo scratch ------------------------------------------
__device__ __nv_bfloat16 g_h1h [T_TOK*D_HID],  g_h1l [T_TOK*D_HID];
__device__ __nv_bfloat16 g_yph [T_TOK*D_HID],  g_ypl [T_TOK*D_HID];
__device__ __nv_bfloat16 g_h2h [T_TOK*D_HID],  g_h2l [T_TOK*D_HID];
__device__ __nv_bfloat16 g_acth[TK*FF],        g_actl[TK*FF];
__device__ __nv_bfloat16 g_inwh [3*D_HID*D_HID], g_inwl [3*D_HID*D_HID];
__device__ __nv_bfloat16 g_outwh[D_HID*D_HID],   g_outwl[D_HID*D_HID];
__device__ __nv_bfloat16 g_w1h [NE*2*FF*D_HID],  g_w1l [NE*2*FF*D_HID];
__device__ __nv_bfloat16 g_w2h [NE*D_HID*FF],    g_w2l [NE*D_HID*FF];

// ---------------- PTX helpers --------------------------------------------------
__device__ __forceinline__ uint32_t smem_u32(const void* p) {
    uint32_t a;
    asm("{ .reg .u64 t; cvta.to.shared.u64 t, %1; cvt.u32.u64 %0, t; }" : "=r"(a) : "l"(p));
    return a;
}
#define CPASYNC(dst, src, sz) \
    asm volatile("cp.async.cg.shared.global [%0], [%1], 16, %2;" :: "r"(dst), "l"(src), "r"(sz))
#define CPCOMMIT() asm volatile("cp.async.commit_group;" ::: "memory")
#define CPWAIT0()  asm volatile("cp.async.wait_group 0;" ::: "memory")
#define LDSM4(r0,r1,r2,r3,addr) \
    asm volatile("ldmatrix.sync.aligned.m8n8.x4.shared.b16 {%0,%1,%2,%3}, [%4];" \
        : "=r"(r0),"=r"(r1),"=r"(r2),"=r"(r3) : "r"(addr))
#define MMA16816(d,a,b0,b1) \
    asm volatile("mma.sync.aligned.m16n8k16.row.col.f32.bf16.bf16.f32 " \
        "{%0,%1,%2,%3}, {%4,%5,%6,%7}, {%8,%9}, {%0,%1,%2,%3};" \
        : "+f"((d)[0]),"+f"((d)[1]),"+f"((d)[2]),"+f"((d)[3]) \
        : "r"((a)[0]),"r"((a)[1]),"r"((a)[2]),"r"((a)[3]), "r"(b0),"r"(b1))

// ---------------- fused add + rmsnorm (+ bf16 hi/lo emit) ----------------------
__global__ void norm_kernel(const float* __restrict__ x, const float* __restrict__ rin,
                            const float* __restrict__ w, float* __restrict__ hout,
                            float* __restrict__ rout,
                            __nv_bfloat16* __restrict__ hhi, __nv_bfloat16* __restrict__ hlo) {
    int t = blockIdx.x;
    int base = threadIdx.x * 4;
    size_t off = (size_t)t * D_HID + base;
    float4 xv = *(const float4*)(x + off);
    float4 rv = *(const float4*)(rin + off);
    float4 s;
    s.x = xv.x + rv.x; s.y = xv.y + rv.y; s.z = xv.z + rv.z; s.w = xv.w + rv.w;
    *(float4*)(rout + off) = s;
    float ss = s.x*s.x + s.y*s.y + s.z*s.z + s.w*s.w;
    #pragma unroll
    for (int o = 16; o > 0; o >>= 1) ss += __shfl_down_sync(0xffffffffu, ss, o);
    __shared__ float sm[8];
    __shared__ float s_inv;
    if ((threadIdx.x & 31) == 0) sm[threadIdx.x >> 5] = ss;
    __syncthreads();
    if (threadIdx.x == 0) {
        float tot = 0.f;
        #pragma unroll
        for (int i = 0; i < 8; i++) tot += sm[i];
        s_inv = rsqrtf(tot / (float)D_HID + EPS);
    }
    __syncthreads();
    float inv = s_inv;
    float4 wv = *(const float4*)(w + base);
    float o[4];
    o[0] = s.x*inv*wv.x; o[1] = s.y*inv*wv.y; o[2] = s.z*inv*wv.z; o[3] = s.w*inv*wv.w;
    *(float4*)(hout + off) = *(float4*)o;
    __nv_bfloat16 h[4], l[4];
    #pragma unroll
    for (int i = 0; i < 4; i++) {
        h[i] = __float2bfloat16(o[i]);
        l[i] = __float2bfloat16(o[i] - __bfloat162float(h[i]));
    }
    *(uint2*)(hhi + off) = *(uint2*)h;
    *(uint2*)(hlo + off) = *(uint2*)l;
}

// ---------------- fp32 -> bf16 hi/lo converter --------------------------------
__global__ void cvt_kernel(const float* __restrict__ src, __nv_bfloat16* __restrict__ hi,
                           __nv_bfloat16* __restrict__ lo, int n) {
    int i = (blockIdx.x * blockDim.x + threadIdx.x) * 4;
    if (i >= n) return;
    float4 v = *(const float4*)(src + i);
    float a[4] = {v.x, v.y, v.z, v.w};
    __nv_bfloat16 h[4], l[4];
    #pragma unroll
    for (int q = 0; q < 4; q++) {
        h[q] = __float2bfloat16(a[q]);
        l[q] = __float2bfloat16(a[q] - __bfloat162float(h[q]));
    }
    *(uint2*)(hi + i) = *(uint2*)h;
    *(uint2*)(lo + i) = *(uint2*)l;
}

// ---------------- split-bf16 mma.sync GEMM: C[m,n] = sum_k A[m,k]*B[n,k] ------
// 3-term: Ahi*Bhi + Ahi*Blo + Alo*Bhi, fp32 accum.
// MODE 0 plain; MODE 1 A-rows gathered via g_rowtok; MODE 2 compact A rows.
// SMEM: per stage 32KB: Ahi[128][32] Alo Bhi Blo (bf16, 64B rows, XOR swizzle).
template<int MODE>
__global__ __launch_bounds__(256, 2)
void mma_gemm(const __nv_bfloat16* __restrict__ Ahi, const __nv_bfloat16* __restrict__ Alo,
              const __nv_bfloat16* __restrict__ Bhi_, const __nv_bfloat16* __restrict__ Blo_,
              float* __restrict__ Cout, int N, int K) {
    extern __shared__ char smb[];
    int tid = threadIdx.x, lane = tid & 31, wid = tid >> 5;

    int cnt = T_TOK, ebase = 0;
    const __nv_bfloat16 *bh_base = Bhi_, *bl_base = Blo_;
    if (MODE > 0) {
        int e = blockIdx.z;
        cnt = g_counts[e]; ebase = g_offsets[e];
        size_t ws = (size_t)N * K;
        bh_base = Bhi_ + (size_t)e * ws;
        bl_base = Blo_ + (size_t)e * ws;
    }
    int m0 = blockIdx.y * 128;
    if (m0 >= cnt) return;
    int n0 = blockIdx.x * 128;

    uint32_t sb = smem_u32(smb);
    const uint32_t STG = 32768;

    // ---- load setup: thread -> (row tid>>1, two 16B chunks) ----
    int lrow = tid >> 1;
    int c0 = (tid & 1) * 2;
    const __nv_bfloat16 *ahp, *alp;
    uint32_t asz = 16;
    if (MODE == 0) {
        int r = m0 + lrow;
        ahp = Ahi + (size_t)r * K; alp = Alo + (size_t)r * K;
    } else if (MODE == 1) {
        int r = m0 + lrow; bool v = (r < cnt);
        int tok = v ? g_rowtok[ebase + r] : 0;
        asz = v ? 16u : 0u;
        ahp = Ahi + (size_t)tok * K; alp = Alo + (size_t)tok * K;
    } else {
        int r = m0 + lrow; bool v = (r < cnt);
        asz = v ? 16u : 0u;
        int rr = ebase + (v ? r : 0);
        ahp = Ahi + (size_t)rr * K; alp = Alo + (size_t)rr * K;
    }
    const __nv_bfloat16* bhp = bh_base + (size_t)(n0 + lrow) * K;
    const __nv_bfloat16* blp = bl_base + (size_t)(n0 + lrow) * K;

    uint32_t sw = (uint32_t)((lrow >> 1) & 3);
    uint32_t d0 = (uint32_t)lrow * 64u + (((uint32_t)c0 ^ sw) << 4);
    uint32_t d1 = (uint32_t)lrow * 64u + ((((uint32_t)c0 + 1u) ^ sw) << 4);

    // ---- ldmatrix address offsets ----
    int wm0 = (wid & 3) * 32, wn0 = (wid >> 2) * 64;
    uint32_t a_off[2][2], b_off[4][2];
    #pragma unroll
    for (int mi = 0; mi < 2; mi++)
        #pragma unroll
        for (int ks = 0; ks < 2; ks++) {
            int r = wm0 + mi * 16 + (lane & 15);
            uint32_t kc = (uint32_t)(ks * 2 + (lane >> 4));
            a_off[mi][ks] = (uint32_t)r * 64u + ((kc ^ ((uint32_t)(r >> 1) & 3u)) << 4);
        }
    #pragma unroll
    for (int pr = 0; pr < 4; pr++)
        #pragma unroll
        for (int ks = 0; ks < 2; ks++) {
            int r = wn0 + pr * 16 + (lane & 7) + ((lane >> 4) ? 8 : 0);
            uint32_t kc = (uint32_t)(ks * 2 + ((lane >> 3) & 1));
            b_off[pr][ks] = (uint32_t)r * 64u + ((kc ^ ((uint32_t)(r >> 1) & 3u)) << 4);
        }

    float acc[2][8][4];
    #pragma unroll
    for (int mi = 0; mi < 2; mi++)
        #pragma unroll
        for (int nt = 0; nt < 8; nt++)
            #pragma unroll
            for (int q = 0; q < 4; q++) acc[mi][nt][q] = 0.f;

    int nch = K / 32;
    // prologue
    {
        uint32_t bb = sb;
        int off = c0 * 16;
        CPASYNC(bb + d0,          (const char*)ahp + off,      asz);
        CPASYNC(bb + d1,          (const char*)ahp + off + 16, asz);
        CPASYNC(bb + 8192 + d0,   (const char*)alp + off,      asz);
        CPASYNC(bb + 8192 + d1,   (const char*)alp + off + 16, asz);
        CPASYNC(bb + 16384 + d0,  (const char*)bhp + off,      16u);
        CPASYNC(bb + 16384 + d1,  (const char*)bhp + off + 16, 16u);
        CPASYNC(bb + 24576 + d0,  (const char*)blp + off,      16u);
        CPASYNC(bb + 24576 + d1,  (const char*)blp + off + 16, 16u);
        CPCOMMIT();
    }

    for (int ch = 0; ch < nch; ch++) {
        CPWAIT0();
        __syncthreads();
        if (ch + 1 < nch) {
            uint32_t bb = sb + (uint32_t)((ch + 1) & 1) * STG;
            int off = (ch + 1) * 64 + c0 * 16;
            CPASYNC(bb + d0,          (const char*)ahp + off,      asz);
            CPASYNC(bb + d1,          (const char*)ahp + off + 16, asz);
            CPASYNC(bb + 8192 + d0,   (const char*)alp + off,      asz);
            CPASYNC(bb + 8192 + d1,   (const char*)alp + off + 16, asz);
            CPASYNC(bb + 16384 + d0,  (const char*)bhp + off,      16u);
            CPASYNC(bb + 16384 + d1,  (const char*)bhp + off + 16, 16u);
            CPASYNC(bb + 24576 + d0,  (const char*)blp + off,      16u);
            CPASYNC(bb + 24576 + d1,  (const char*)blp + off + 16, 16u);
            CPCOMMIT();
        }
        uint32_t base = sb + (uint32_t)(ch & 1) * STG;
        #pragma unroll
        for (int ks = 0; ks < 2; ks++) {
            uint32_t ah[2][4], al[2][4];
            #pragma unroll
            for (int mi = 0; mi < 2; mi++) {
                LDSM4(ah[mi][0], ah[mi][1], ah[mi][2], ah[mi][3], base + a_off[mi][ks]);
                LDSM4(al[mi][0], al[mi][1], al[mi][2], al[mi][3], base + 8192 + a_off[mi][ks]);
            }
            #pragma unroll
            for (int pr = 0; pr < 4; pr++) {
                uint32_t bh0, bh1, bh2, bh3, bl0, bl1, bl2, bl3;
                LDSM4(bh0, bh1, bh2, bh3, base + 16384 + b_off[pr][ks]);
                LDSM4(bl0, bl1, bl2, bl3, base + 24576 + b_off[pr][ks]);
                #pragma unroll
                for (int mi = 0; mi < 2; mi++) {
                    MMA16816(acc[mi][pr*2],   ah[mi], bh0, bh1);
                    MMA16816(acc[mi][pr*2],   ah[mi], bl0, bl1);
                    MMA16816(acc[mi][pr*2],   al[mi], bh0, bh1);
                    MMA16816(acc[mi][pr*2+1], ah[mi], bh2, bh3);
                    MMA16816(acc[mi][pr*2+1], ah[mi], bl2, bl3);
                    MMA16816(acc[mi][pr*2+1], al[mi], bh2, bh3);
                }
            }
        }
        __syncthreads();
    }

    // epilogue
    int grp = lane >> 2, tig = lane & 3;
    #pragma unroll
    for (int mi = 0; mi < 2; mi++) {
        int rl0 = wm0 + mi * 16 + grp;
        #pragma unroll
        for (int nt = 0; nt < 8; nt++) {
            int col = n0 + wn0 + nt * 8 + tig * 2;
            int r0i = m0 + rl0, r1i = r0i + 8;
            bool v0 = (MODE == 0) || (r0i < cnt);
            bool v1 = (MODE == 0) || (r1i < cnt);
            size_t g0 = (size_t)((MODE == 0) ? r0i : ebase + r0i) * N + col;
            size_t g1 = (size_t)((MODE == 0) ? r1i : ebase + r1i) * N + col;
            if (v0) { float2 p = make_float2(acc[mi][nt][0], acc[mi][nt][1]); *(float2*)(Cout + g0) = p; }
            if (v1) { float2 p = make_float2(acc[mi][nt][2], acc[mi][nt][3]); *(float2*)(Cout + g1) = p; }
        }
    }
}

// ---------------- short conv + C-gate -> ypre hi/lo ---------------------------
__global__ void conv_kernel(const float* __restrict__ convw) {
    int i = blockIdx.x * blockDim.x + threadIdx.x;
    if (i >= T_TOK * D_HID) return;
    int t = i / D_HID, d = i % D_HID;
    float w0 = convw[d*CL + 0], w1 = convw[d*CL + 1], w2 = convw[d*CL + 2];
    const float* bc = g_bcx;
    size_t r0 = (size_t)t * 3 * D_HID;
    float acc = w2 * bc[r0 + d] * bc[r0 + 2*D_HID + d];
    if (t >= 1) { size_t r1 = r0 - 3*D_HID; acc += w1 * bc[r1 + d] * bc[r1 + 2*D_HID + d]; }
    if (t >= 2) { size_t r2 = r0 - 6*D_HID; acc += w0 * bc[r2 + d] * bc[r2 + 2*D_HID + d]; }
    float v = bc[r0 + D_HID + d] * acc;
    __nv_bfloat16 h = __float2bfloat16(v);
    g_yph[i] = h;
    g_ypl[i] = __float2bfloat16(v - __bfloat162float(h));
}

// ---------------- gating ------------------------------------------------------
__global__ void zero_counts_kernel() {
    if (threadIdx.x < NE) g_counts[threadIdx.x] = 0;
}

__global__ void gate_kernel(const float* __restrict__ h2, const float* __restrict__ gw,
                            const float* __restrict__ gb) {
    int t = blockIdx.x;
    int warp = threadIdx.x >> 5, lane = threadIdx.x & 31;
    const float* hr = h2 + (size_t)t * D_HID;
    const float* wr = gw + (size_t)warp * D_HID;
    float p = 0.f;
    for (int k = lane; k < D_HID; k += 32) p += hr[k] * wr[k];
    #pragma unroll
    for (int o = 16; o > 0; o >>= 1) p += __shfl_down_sync(0xffffffffu, p, o);
    __shared__ float s_logit[NE];
    if (lane == 0) s_logit[warp] = p;
    __syncthreads();
    if (threadIdx.x == 0) {
        float sc[NE], ch[NE];
        bool used[NE];
        #pragma unroll
        for (int e = 0; e < NE; e++) {
            float s = 1.f / (1.f + expf(-s_logit[e]));
            sc[e] = s; ch[e] = s + gb[e]; used[e] = false;
        }
        int idx[TOPK]; float wsum = 0.f;
        #pragma unroll
        for (int k = 0; k < TOPK; k++) {
            float best = -1e30f; int bi = 0;
            #pragma unroll
            for (int e = 0; e < NE; e++)
                if (!used[e] && ch[e] > best) { best = ch[e]; bi = e; }
            used[bi] = true; idx[k] = bi; wsum += sc[bi];
        }
        float inv = 1.f / (wsum + 1e-20f);
        #pragma unroll
        for (int k = 0; k < TOPK; k++) {
            g_topi[t*TOPK + k] = idx[k];
            g_topw[t*TOPK + k] = sc[idx[k]] * inv;
            atomicAdd(&g_counts[idx[k]], 1);
        }
    }
}

__global__ void scan_kernel() {
    if (threadIdx.x == 0) {
        int acc = 0;
        for (int e = 0; e < NE; e++) { g_offsets[e] = acc; acc += g_counts[e]; }
    }
    if (threadIdx.x < NE) g_fill[threadIdx.x] = 0;
}

__global__ void fill_kernel() {
    int i = blockIdx.x * blockDim.x + threadIdx.x;
    if (i >= TK) return;
    int e = g_topi[i];
    int pos = g_offsets[e] + atomicAdd(&g_fill[e], 1);
    g_rowtok[pos] = i / TOPK;
    g_slot[i] = pos;
}

// ---------------- SiLU(g)*u -> act hi/lo ---------------------------------------
__global__ void act_kernel() {
    int i = blockIdx.x * blockDim.x + threadIdx.x;
    if (i >= TK * FF) return;
    int r = i / FF, f = i % FF;
    float g = g_gu[(size_t)r * (2*FF) + f];
    float u = g_gu[(size_t)r * (2*FF) + FF + f];
    float v = (g / (1.f + expf(-g))) * u;
    __nv_bfloat16 h = __float2bfloat16(v);
    g_acth[i] = h;
    g_actl[i] = __float2bfloat16(v - __bfloat162float(h));
}

// ---------------- combine ------------------------------------------------------
__global__ void combine_kernel(float* __restrict__ out) {
    int i = blockIdx.x * blockDim.x + threadIdx.x;
    if (i >= T_TOK * D_HID) return;
    int t = i / D_HID, d = i % D_HID;
    float s = 0.f;
    #pragma unroll
    for (int k = 0; k < TOPK; k++)
        s += g_topw[t*TOPK + k] * g_ye[(size_t)g_slot[t*TOPK + k] * D_HID + d];
    out[i] = s;   // SCALE = 1.0
}

// ---------------- launch -------------------------------------------------------
#define GEMM_SMEM (2*32768)

template<typename T> static T* sym(const void* s) {
    void* p = nullptr;
    cudaGetSymbolAddress(&p, s);
    return (T*)p;
}

extern "C" void kernel_launch(void* const* d_in, const int* in_sizes, int n_in,
                              void* d_out, int out_size) {
    const float* hs    = (const float*)d_in[0];
    const float* res   = (const float*)d_in[1];
    const float* opw   = (const float*)d_in[2];
    const float* ffnw  = (const float*)d_in[3];
    const float* inw   = (const float*)d_in[4];
    const float* convw = (const float*)d_in[5];
    const float* outw  = (const float*)d_in[6];
    const float* gw    = (const float*)d_in[7];
    const float* gb    = (const float*)d_in[8];
    const float* w1    = (const float*)d_in[9];
    const float* w2    = (const float*)d_in[10];
    float* out = (float*)d_out;
    float* res_out = out + (size_t)T_TOK * D_HID;

    float* p_h1   = sym<float>(&g_h1);
    float* p_res1 = sym<float>(&g_res1);
    float* p_bcx  = sym<float>(&g_bcx);
    float* p_y    = sym<float>(&g_y);
    float* p_h2   = sym<float>(&g_h2);
    float* p_gu   = sym<float>(&g_gu);
    float* p_ye   = sym<float>(&g_ye);
    __nv_bfloat16* p_h1h  = sym<__nv_bfloat16>(&g_h1h);
    __nv_bfloat16* p_h1l  = sym<__nv_bfloat16>(&g_h1l);
    __nv_bfloat16* p_yph  = sym<__nv_bfloat16>(&g_yph);
    __nv_bfloat16* p_ypl  = sym<__nv_bfloat16>(&g_ypl);
    __nv_bfloat16* p_h2h  = sym<__nv_bfloat16>(&g_h2h);
    __nv_bfloat16* p_h2l  = sym<__nv_bfloat16>(&g_h2l);
    __nv_bfloat16* p_acth = sym<__nv_bfloat16>(&g_acth);
    __nv_bfloat16* p_actl = sym<__nv_bfloat16>(&g_actl);
    __nv_bfloat16* p_inwh = sym<__nv_bfloat16>(&g_inwh);
    __nv_bfloat16* p_inwl = sym<__nv_bfloat16>(&g_inwl);
    __nv_bfloat16* p_outwh= sym<__nv_bfloat16>(&g_outwh);
    __nv_bfloat16* p_outwl= sym<__nv_bfloat16>(&g_outwl);
    __nv_bfloat16* p_w1h  = sym<__nv_bfloat16>(&g_w1h);
    __nv_bfloat16* p_w1l  = sym<__nv_bfloat16>(&g_w1l);
    __nv_bfloat16* p_w2h  = sym<__nv_bfloat16>(&g_w2h);
    __nv_bfloat16* p_w2l  = sym<__nv_bfloat16>(&g_w2l);

    cudaFuncSetAttribute(mma_gemm<0>, cudaFuncAttributeMaxDynamicSharedMemorySize, GEMM_SMEM);
    cudaFuncSetAttribute(mma_gemm<1>, cudaFuncAttributeMaxDynamicSharedMemorySize, GEMM_SMEM);
    cudaFuncSetAttribute(mma_gemm<2>, cudaFuncAttributeMaxDynamicSharedMemorySize, GEMM_SMEM);

    // weight converts (independent of activations)
    {
        int n;
        n = 3*D_HID*D_HID; cvt_kernel<<<(n/4 + 255)/256, 256>>>(inw,  p_inwh,  p_inwl,  n);
        n = D_HID*D_HID;   cvt_kernel<<<(n/4 + 255)/256, 256>>>(outw, p_outwh, p_outwl, n);
        n = NE*2*FF*D_HID; cvt_kernel<<<(n/4 + 255)/256, 256>>>(w1,   p_w1h,   p_w1l,   n);
        n = NE*D_HID*FF;   cvt_kernel<<<(n/4 + 255)/256, 256>>>(w2,   p_w2h,   p_w2l,   n);
    }

    // 1) h1 = rmsnorm(hs + res); res1 = hs + res
    norm_kernel<<<T_TOK, 256>>>(hs, res, opw, p_h1, p_res1, p_h1h, p_h1l);

    // 2) bcx = h1 @ in_proj^T
    mma_gemm<0><<<dim3(3*D_HID/128, T_TOK/128, 1), 256, GEMM_SMEM>>>(
        p_h1h, p_h1l, p_inwh, p_inwl, p_bcx, 3*D_HID, D_HID);

    // 3) short conv + C gate -> ypre hi/lo
    conv_kernel<<<(T_TOK*D_HID + 255)/256, 256>>>(convw);

    // 4) y = ypre @ out_proj^T
    mma_gemm<0><<<dim3(D_HID/128, T_TOK/128, 1), 256, GEMM_SMEM>>>(
        p_yph, p_ypl, p_outwh, p_outwl, p_y, D_HID, D_HID);

    // 5) h2 = rmsnorm(y + res1); residual out
    norm_kernel<<<T_TOK, 256>>>(p_y, p_res1, ffnw, p_h2, res_out, p_h2h, p_h2l);

    // 6-9) gating + bucketing
    zero_counts_kernel<<<1, 32>>>();
    gate_kernel<<<T_TOK, NE*32>>>(p_h2, gw, gb);
    scan_kernel<<<1, 32>>>();
    fill_kernel<<<(TK + 255)/256, 256>>>();

    // 10) gu = gather(h2) @ w1[e]^T
    mma_gemm<1><<<dim3(2*FF/128, T_TOK/128, NE), 256, GEMM_SMEM>>>(
        p_h2h, p_h2l, p_w1h, p_w1l, p_gu, 2*FF, D_HID);

    // 11) act = silu(g) * u  -> hi/lo
    act_kernel<<<(TK*FF + 255)/256, 256>>>();

    // 12) ye = act @ w2[e]^T; combine
    mma_gemm<2><<<dim3(D_HID/128, T_TOK/128, NE), 256, GEMM_SMEM>>>(
        p_acth, p_actl, p_w2h, p_w2l, p_ye, D_HID, FF);
    combine_kernel<<<(T_TOK*D_HID + 255)/256, 256>>>(out);
}

// round 8
// speedup vs baseline: 2.3237x; 1.0064x over previous
#include <cuda_runtime.h>
#include <cuda_bf16.h>
#include <math.h>
#include <stdint.h>

#define T_TOK 2048
#define D_HID 1024
#define FF    512
#define NE    16
#define TOPK  4
#define CL    3
#define EPS   1e-5f
#define TK    (T_TOK*TOPK)

// ---------------- fp32 scratch ------------------------------------------------
__device__ float g_h1  [T_TOK*D_HID];
__device__ float g_res1[T_TOK*D_HID];
__device__ float g_bcx [T_TOK*3*D_HID];
__device__ float g_y   [T_TOK*D_HID];
__device__ float g_h2  [T_TOK*D_HID];
__device__ float g_gu  [TK*2*FF];
__device__ float g_ye  [TK*D_HID];
__device__ int   g_topi[TK];
__device__ float g_topw[TK];
__device__ int   g_counts[NE];
__device__ int   g_offsets[NE];
__device__ int   g_fill[NE];
__device__ int   g_rowtok[TK];
__device__ int   g_slot[TK];

// ---------------- bf16 hi/lo activation scratch --------------------------------
__device__ __nv_bfloat16 g_h1h [T_TOK*D_HID],  g_h1l [T_TOK*D_HID];
__device__ __nv_bfloat16 g_yph [T_TOK*D_HID],  g_ypl [T_TOK*D_HID];
__device__ __nv_bfloat16 g_h2h [T_TOK*D_HID],  g_h2l [T_TOK*D_HID];
__device__ __nv_bfloat16 g_acth[TK*FF],        g_actl[TK*FF];

// ---------------- PTX helpers --------------------------------------------------
__device__ __forceinline__ uint32_t smem_u32(const void* p) {
    uint32_t a;
    asm("{ .reg .u64 t; cvta.to.shared.u64 t, %1; cvt.u32.u64 %0, t; }" : "=r"(a) : "l"(p));
    return a;
}
#define CPASYNC(dst, src, sz) \
    asm volatile("cp.async.cg.shared.global [%0], [%1], 16, %2;" :: "r"(dst), "l"(src), "r"(sz))
#define CPCOMMIT() asm volatile("cp.async.commit_group;" ::: "memory")
#define CPWAIT0()  asm volatile("cp.async.wait_group 0;" ::: "memory")
#define LDSM4(r0,r1,r2,r3,addr) \
    asm volatile("ldmatrix.sync.aligned.m8n8.x4.shared.b16 {%0,%1,%2,%3}, [%4];" \
        : "=r"(r0),"=r"(r1),"=r"(r2),"=r"(r3) : "r"(addr))
#define MMA16816(d,a,b0,b1) \
    asm volatile("mma.sync.aligned.m16n8k16.row.col.f32.bf16.bf16.f32 " \
        "{%0,%1,%2,%3}, {%4,%5,%6,%7}, {%8,%9}, {%0,%1,%2,%3};" \
        : "+f"((d)[0]),"+f"((d)[1]),"+f"((d)[2]),"+f"((d)[3]) \
        : "r"((a)[0]),"r"((a)[1]),"r"((a)[2]),"r"((a)[3]), "r"(b0),"r"(b1))
#define LDS128F(v, addr) \
    asm volatile("ld.shared.v4.f32 {%0,%1,%2,%3}, [%4];" \
        : "=f"((v).x),"=f"((v).y),"=f"((v).z),"=f"((v).w) : "r"(addr))
#define STS128U(addr, a0,a1,a2,a3) \
    asm volatile("st.shared.v4.b32 [%0], {%1,%2,%3,%4};" \
        :: "r"(addr), "r"(a0),"r"(a1),"r"(a2),"r"(a3) : "memory")

// ---------------- fused add + rmsnorm (+ bf16 hi/lo emit) ----------------------
__global__ void norm_kernel(const float* __restrict__ x, const float* __restrict__ rin,
                            const float* __restrict__ w, float* __restrict__ hout,
                            float* __restrict__ rout,
                            __nv_bfloat16* __restrict__ hhi, __nv_bfloat16* __restrict__ hlo) {
    int t = blockIdx.x;
    int base = threadIdx.x * 4;
    size_t off = (size_t)t * D_HID + base;
    float4 xv = *(const float4*)(x + off);
    float4 rv = *(const float4*)(rin + off);
    float4 s;
    s.x = xv.x + rv.x; s.y = xv.y + rv.y; s.z = xv.z + rv.z; s.w = xv.w + rv.w;
    *(float4*)(rout + off) = s;
    float ss = s.x*s.x + s.y*s.y + s.z*s.z + s.w*s.w;
    #pragma unroll
    for (int o = 16; o > 0; o >>= 1) ss += __shfl_down_sync(0xffffffffu, ss, o);
    __shared__ float sm[8];
    __shared__ float s_inv;
    if ((threadIdx.x & 31) == 0) sm[threadIdx.x >> 5] = ss;
    __syncthreads();
    if (threadIdx.x == 0) {
        float tot = 0.f;
        #pragma unroll
        for (int i = 0; i < 8; i++) tot += sm[i];
        s_inv = rsqrtf(tot / (float)D_HID + EPS);
    }
    __syncthreads();
    float inv = s_inv;
    float4 wv = *(const float4*)(w + base);
    float o[4];
    o[0] = s.x*inv*wv.x; o[1] = s.y*inv*wv.y; o[2] = s.z*inv*wv.z; o[3] = s.w*inv*wv.w;
    *(float4*)(hout + off) = *(float4*)o;
    __nv_bfloat16 h[4], l[4];
    #pragma unroll
    for (int i = 0; i < 4; i++) {
        h[i] = __float2bfloat16(o[i]);
        l[i] = __float2bfloat16(o[i] - __bfloat162float(h[i]));
    }
    *(uint2*)(hhi + off) = *(uint2*)h;
    *(uint2*)(hlo + off) = *(uint2*)l;
}

// ---------------- split-bf16 mma.sync GEMM: C[m,n] = sum_k A[m,k]*B[n,k] ------
// A: pre-split hi/lo bf16 (activations). B: fp32 weights, converted to hi/lo
// bf16 on the fly inside the mainloop (hidden under tensor shadow).
// 3-term: Ahi*Bhi + Ahi*Blo + Alo*Bhi, fp32 accum.
// MODE 0 plain; MODE 1 A-rows gathered via g_rowtok; MODE 2 compact A rows.
#define AHI_OFF 0u
#define ALO_OFF 8192u
#define BHI_OFF 16384u
#define BLO_OFF 24576u
#define BF32_OFF 32768u
#define STG 49152u

template<int MODE>
__global__ __launch_bounds__(256, 2)
void mma_gemm(const __nv_bfloat16* __restrict__ Ahi, const __nv_bfloat16* __restrict__ Alo,
              const float* __restrict__ Bf32, float* __restrict__ Cout, int N, int K) {
    extern __shared__ char smb[];
    int tid = threadIdx.x, lane = tid & 31, wid = tid >> 5;

    int cnt = T_TOK, ebase = 0;
    const float* bbase = Bf32;
    if (MODE > 0) {
        int e = blockIdx.z;
        cnt = g_counts[e]; ebase = g_offsets[e];
        bbase = Bf32 + (size_t)e * (size_t)N * K;
    }
    int m0 = blockIdx.y * 128;
    if (m0 >= cnt) return;
    int n0 = blockIdx.x * 128;

    uint32_t sb = smem_u32(smb);

    // ---- load mapping: row = tid>>1, half = tid&1 ----
    int lrow = tid >> 1;
    int lhalf = tid & 1;
    int c0 = lhalf * 2;                    // bf16 16B-chunk base within 64B row
    const __nv_bfloat16 *ahp, *alp;
    uint32_t asz = 16;
    if (MODE == 0) {
        int r = m0 + lrow;
        ahp = Ahi + (size_t)r * K; alp = Alo + (size_t)r * K;
    } else if (MODE == 1) {
        int r = m0 + lrow; bool v = (r < cnt);
        int tok = v ? g_rowtok[ebase + r] : 0;
        asz = v ? 16u : 0u;
        ahp = Ahi + (size_t)tok * K; alp = Alo + (size_t)tok * K;
    } else {
        int r = m0 + lrow; bool v = (r < cnt);
        asz = v ? 16u : 0u;
        int rr = ebase + (v ? r : 0);
        ahp = Ahi + (size_t)rr * K; alp = Alo + (size_t)rr * K;
    }
    const float* bfp = bbase + (size_t)(n0 + lrow) * K;

    uint32_t swr = (uint32_t)((lrow >> 1) & 3);
    uint32_t d0 = (uint32_t)lrow * 64u + (((uint32_t)c0 ^ swr) << 4);
    uint32_t d1 = (uint32_t)lrow * 64u + ((((uint32_t)c0 + 1u) ^ swr) << 4);
    // fp32 staging dst offsets (swizzled; conflict-free for 128B rows)
    uint32_t bq[4];
    #pragma unroll
    for (int q = 0; q < 4; q++)
        bq[q] = (uint32_t)lrow * 128u + ((uint32_t)((lhalf*4 + q) ^ (lrow & 7)) << 4);

    // ---- ldmatrix address offsets ----
    int wm0 = (wid & 3) * 32, wn0 = (wid >> 2) * 64;
    uint32_t a_off[2][2], b_off[4][2];
    #pragma unroll
    for (int mi = 0; mi < 2; mi++)
        #pragma unroll
        for (int ks = 0; ks < 2; ks++) {
            int r = wm0 + mi * 16 + (lane & 15);
            uint32_t kc = (uint32_t)(ks * 2 + (lane >> 4));
            a_off[mi][ks] = (uint32_t)r * 64u + ((kc ^ ((uint32_t)(r >> 1) & 3u)) << 4);
        }
    #pragma unroll
    for (int pr = 0; pr < 4; pr++)
        #pragma unroll
        for (int ks = 0; ks < 2; ks++) {
            int r = wn0 + pr * 16 + (lane & 7) + ((lane >> 4) ? 8 : 0);
            uint32_t kc = (uint32_t)(ks * 2 + ((lane >> 3) & 1));
            b_off[pr][ks] = (uint32_t)r * 64u + ((kc ^ ((uint32_t)(r >> 1) & 3u)) << 4);
        }

    float acc[2][8][4];
    #pragma unroll
    for (int mi = 0; mi < 2; mi++)
        #pragma unroll
        for (int nt = 0; nt < 8; nt++)
            #pragma unroll
            for (int q = 0; q < 4; q++) acc[mi][nt][q] = 0.f;

    int nch = K / 32;
    // prologue: issue A hi/lo + B fp32 for chunk 0 -> stage 0
    {
        uint32_t bb = sb;
        int aoff = c0 * 16;                    // per-thread chunk offset (R6 bugfix)
        CPASYNC(bb + AHI_OFF + d0, (const char*)ahp + aoff,      asz);
        CPASYNC(bb + AHI_OFF + d1, (const char*)ahp + aoff + 16, asz);
        CPASYNC(bb + ALO_OFF + d0, (const char*)alp + aoff,      asz);
        CPASYNC(bb + ALO_OFF + d1, (const char*)alp + aoff + 16, asz);
        const char* bs = (const char*)bfp + lhalf * 64;
        #pragma unroll
        for (int q = 0; q < 4; q++)
            CPASYNC(bb + BF32_OFF + bq[q], bs + q * 16, 16u);
        CPCOMMIT();
    }

    for (int ch = 0; ch < nch; ch++) {
        CPWAIT0();
        __syncthreads();                    // stage s: A hi/lo + B fp32 landed
        uint32_t stb = sb + (uint32_t)(ch & 1) * STG;
        // issue next chunk's cp.asyncs -> other stage
        if (ch + 1 < nch) {
            uint32_t bb = sb + (uint32_t)((ch + 1) & 1) * STG;
            int aoff = (ch + 1) * 64 + c0 * 16;
            CPASYNC(bb + AHI_OFF + d0, (const char*)ahp + aoff,      asz);
            CPASYNC(bb + AHI_OFF + d1, (const char*)ahp + aoff + 16, asz);
            CPASYNC(bb + ALO_OFF + d0, (const char*)alp + aoff,      asz);
            CPASYNC(bb + ALO_OFF + d1, (const char*)alp + aoff + 16, asz);
            const char* bs = (const char*)bfp + (ch + 1) * 128 + lhalf * 64;
            #pragma unroll
            for (int q = 0; q < 4; q++)
                CPASYNC(bb + BF32_OFF + bq[q], bs + q * 16, 16u);
            CPCOMMIT();
        }
        // convert B fp32(stage s) -> Bhi/Blo(stage s)
        {
            float f[16];
            #pragma unroll
            for (int q = 0; q < 4; q++) {
                float4 v;
                LDS128F(v, stb + BF32_OFF + bq[q]);
                f[4*q+0] = v.x; f[4*q+1] = v.y; f[4*q+2] = v.z; f[4*q+3] = v.w;
            }
            uint32_t hi[8], lo[8];
            #pragma unroll
            for (int i = 0; i < 8; i++) {
                __nv_bfloat162 hp = __floats2bfloat162_rn(f[2*i], f[2*i+1]);
                uint32_t hb = *(uint32_t*)&hp;
                hi[i] = hb;
                float r0 = f[2*i]   - __uint_as_float(hb << 16);
                float r1 = f[2*i+1] - __uint_as_float(hb & 0xFFFF0000u);
                __nv_bfloat162 lp = __floats2bfloat162_rn(r0, r1);
                lo[i] = *(uint32_t*)&lp;
            }
            uint32_t rb = (uint32_t)lrow * 64u;
            uint32_t cA = rb + (((uint32_t)c0 ^ swr) << 4);
            uint32_t cB = rb + ((((uint32_t)c0 + 1u) ^ swr) << 4);
            STS128U(stb + BHI_OFF + cA, hi[0], hi[1], hi[2], hi[3]);
            STS128U(stb + BHI_OFF + cB, hi[4], hi[5], hi[6], hi[7]);
            STS128U(stb + BLO_OFF + cA, lo[0], lo[1], lo[2], lo[3]);
            STS128U(stb + BLO_OFF + cB, lo[4], lo[5], lo[6], lo[7]);
        }
        __syncthreads();                    // Bhi/Blo(stage s) visible
        // ---- mma over stage s ----
        #pragma unroll
        for (int ks = 0; ks < 2; ks++) {
            uint32_t ah[2][4], al[2][4];
            #pragma unroll
            for (int mi = 0; mi < 2; mi++) {
                LDSM4(ah[mi][0], ah[mi][1], ah[mi][2], ah[mi][3], stb + AHI_OFF + a_off[mi][ks]);
                LDSM4(al[mi][0], al[mi][1], al[mi][2], al[mi][3], stb + ALO_OFF + a_off[mi][ks]);
            }
            #pragma unroll
            for (int pr = 0; pr < 4; pr++) {
                uint32_t bh0, bh1, bh2, bh3, bl0, bl1, bl2, bl3;
                LDSM4(bh0, bh1, bh2, bh3, stb + BHI_OFF + b_off[pr][ks]);
                LDSM4(bl0, bl1, bl2, bl3, stb + BLO_OFF + b_off[pr][ks]);
                #pragma unroll
                for (int mi = 0; mi < 2; mi++) {
                    MMA16816(acc[mi][pr*2],   ah[mi], bh0, bh1);
                    MMA16816(acc[mi][pr*2],   ah[mi], bl0, bl1);
                    MMA16816(acc[mi][pr*2],   al[mi], bh0, bh1);
                    MMA16816(acc[mi][pr*2+1], ah[mi], bh2, bh3);
                    MMA16816(acc[mi][pr*2+1], ah[mi], bl2, bl3);
                    MMA16816(acc[mi][pr*2+1], al[mi], bh2, bh3);
                }
            }
        }
    }

    // epilogue
    int grp = lane >> 2, tig = lane & 3;
    #pragma unroll
    for (int mi = 0; mi < 2; mi++) {
        int rl0 = wm0 + mi * 16 + grp;
        #pragma unroll
        for (int nt = 0; nt < 8; nt++) {
            int col = n0 + wn0 + nt * 8 + tig * 2;
            int r0i = m0 + rl0, r1i = r0i + 8;
            bool v0 = (MODE == 0) || (r0i < cnt);
            bool v1 = (MODE == 0) || (r1i < cnt);
            size_t g0 = (size_t)((MODE == 0) ? r0i : ebase + r0i) * N + col;
            size_t g1 = (size_t)((MODE == 0) ? r1i : ebase + r1i) * N + col;
            if (v0) { float2 p = make_float2(acc[mi][nt][0], acc[mi][nt][1]); *(float2*)(Cout + g0) = p; }
            if (v1) { float2 p = make_float2(acc[mi][nt][2], acc[mi][nt][3]); *(float2*)(Cout + g1) = p; }
        }
    }
}

// ---------------- short conv + C-gate -> ypre hi/lo ---------------------------
__global__ void conv_kernel(const float* __restrict__ convw) {
    int i = blockIdx.x * blockDim.x + threadIdx.x;
    if (i >= T_TOK * D_HID) return;
    int t = i / D_HID, d = i % D_HID;
    float w0 = convw[d*CL + 0], w1 = convw[d*CL + 1], w2 = convw[d*CL + 2];
    const float* bc = g_bcx;
    size_t r0 = (size_t)t * 3 * D_HID;
    float acc = w2 * bc[r0 + d] * bc[r0 + 2*D_HID + d];
    if (t >= 1) { size_t r1 = r0 - 3*D_HID; acc += w1 * bc[r1 + d] * bc[r1 + 2*D_HID + d]; }
    if (t >= 2) { size_t r2 = r0 - 6*D_HID; acc += w0 * bc[r2 + d] * bc[r2 + 2*D_HID + d]; }
    float v = bc[r0 + D_HID + d] * acc;
    __nv_bfloat16 h = __float2bfloat16(v);
    g_yph[i] = h;
    g_ypl[i] = __float2bfloat16(v - __bfloat162float(h));
}

// ---------------- gating ------------------------------------------------------
__global__ void zero_counts_kernel() {
    if (threadIdx.x < NE) g_counts[threadIdx.x] = 0;
}

__global__ void gate_kernel(const float* __restrict__ h2, const float* __restrict__ gw,
                            const float* __restrict__ gb) {
    int t = blockIdx.x;
    int warp = threadIdx.x >> 5, lane = threadIdx.x & 31;
    const float* hr = h2 + (size_t)t * D_HID;
    const float* wr = gw + (size_t)warp * D_HID;
    float p = 0.f;
    for (int k = lane; k < D_HID; k += 32) p += hr[k] * wr[k];
    #pragma unroll
    for (int o = 16; o > 0; o >>= 1) p += __shfl_down_sync(0xffffffffu, p, o);
    __shared__ float s_logit[NE];
    if (lane == 0) s_logit[warp] = p;
    __syncthreads();
    if (threadIdx.x == 0) {
        float sc[NE], ch[NE];
        bool used[NE];
        #pragma unroll
        for (int e = 0; e < NE; e++) {
            float s = 1.f / (1.f + expf(-s_logit[e]));
            sc[e] = s; ch[e] = s + gb[e]; used[e] = false;
        }
        int idx[TOPK]; float wsum = 0.f;
        #pragma unroll
        for (int k = 0; k < TOPK; k++) {
            float best = -1e30f; int bi = 0;
            #pragma unroll
            for (int e = 0; e < NE; e++)
                if (!used[e] && ch[e] > best) { best = ch[e]; bi = e; }
            used[bi] = true; idx[k] = bi; wsum += sc[bi];
        }
        float inv = 1.f / (wsum + 1e-20f);
        #pragma unroll
        for (int k = 0; k < TOPK; k++) {
            g_topi[t*TOPK + k] = idx[k];
            g_topw[t*TOPK + k] = sc[idx[k]] * inv;
            atomicAdd(&g_counts[idx[k]], 1);
        }
    }
}

__global__ void scan_kernel() {
    if (threadIdx.x == 0) {
        int acc = 0;
        for (int e = 0; e < NE; e++) { g_offsets[e] = acc; acc += g_counts[e]; }
    }
    if (threadIdx.x < NE) g_fill[threadIdx.x] = 0;
}

__global__ void fill_kernel() {
    int i = blockIdx.x * blockDim.x + threadIdx.x;
    if (i >= TK) return;
    int e = g_topi[i];
    int pos = g_offsets[e] + atomicAdd(&g_fill[e], 1);
    g_rowtok[pos] = i / TOPK;
    g_slot[i] = pos;
}

// ---------------- SiLU(g)*u -> act hi/lo ---------------------------------------
__global__ void act_kernel() {
    int i = blockIdx.x * blockDim.x + threadIdx.x;
    if (i >= TK * FF) return;
    int r = i / FF, f = i % FF;
    float g = g_gu[(size_t)r * (2*FF) + f];
    float u = g_gu[(size_t)r * (2*FF) + FF + f];
    float v = (g / (1.f + expf(-g))) * u;
    __nv_bfloat16 h = __float2bfloat16(v);
    g_acth[i] = h;
    g_actl[i] = __float2bfloat16(v - __bfloat162float(h));
}

// ---------------- combine ------------------------------------------------------
__global__ void combine_kernel(float* __restrict__ out) {
    int i = blockIdx.x * blockDim.x + threadIdx.x;
    if (i >= T_TOK * D_HID) return;
    int t = i / D_HID, d = i % D_HID;
    float s = 0.f;
    #pragma unroll
    for (int k = 0; k < TOPK; k++)
        s += g_topw[t*TOPK + k] * g_ye[(size_t)g_slot[t*TOPK + k] * D_HID + d];
    out[i] = s;   // SCALE = 1.0
}

// ---------------- launch -------------------------------------------------------
#define GEMM_SMEM (2*49152)

template<typename T> static T* sym(const void* s) {
    void* p = nullptr;
    cudaGetSymbolAddress(&p, s);
    return (T*)p;
}

extern "C" void kernel_launch(void* const* d_in, const int* in_sizes, int n_in,
                              void* d_out, int out_size) {
    const float* hs    = (const float*)d_in[0];
    const float* res   = (const float*)d_in[1];
    const float* opw   = (const float*)d_in[2];
    const float* ffnw  = (const float*)d_in[3];
    const float* inw   = (const float*)d_in[4];
    const float* convw = (const float*)d_in[5];
    const float* outw  = (const float*)d_in[6];
    const float* gw    = (const float*)d_in[7];
    const float* gb    = (const float*)d_in[8];
    const float* w1    = (const float*)d_in[9];
    const float* w2    = (const float*)d_in[10];
    float* out = (float*)d_out;
    float* res_out = out + (size_t)T_TOK * D_HID;

    float* p_h1   = sym<float>(&g_h1);
    float* p_res1 = sym<float>(&g_res1);
    float* p_bcx  = sym<float>(&g_bcx);
    float* p_y    = sym<float>(&g_y);
    float* p_h2   = sym<float>(&g_h2);
    float* p_gu   = sym<float>(&g_gu);
    float* p_ye   = sym<float>(&g_ye);
    __nv_bfloat16* p_h1h  = sym<__nv_bfloat16>(&g_h1h);
    __nv_bfloat16* p_h1l  = sym<__nv_bfloat16>(&g_h1l);
    __nv_bfloat16* p_yph  = sym<__nv_bfloat16>(&g_yph);
    __nv_bfloat16* p_ypl  = sym<__nv_bfloat16>(&g_ypl);
    __nv_bfloat16* p_h2h  = sym<__nv_bfloat16>(&g_h2h);
    __nv_bfloat16* p_h2l  = sym<__nv_bfloat16>(&g_h2l);
    __nv_bfloat16* p_acth = sym<__nv_bfloat16>(&g_acth);
    __nv_bfloat16* p_actl = sym<__nv_bfloat16>(&g_actl);

    cudaFuncSetAttribute(mma_gemm<0>, cudaFuncAttributeMaxDynamicSharedMemorySize, GEMM_SMEM);
    cudaFuncSetAttribute(mma_gemm<1>, cudaFuncAttributeMaxDynamicSharedMemorySize, GEMM_SMEM);
    cudaFuncSetAttribute(mma_gemm<2>, cudaFuncAttributeMaxDynamicSharedMemorySize, GEMM_SMEM);

    // 1) h1 = rmsnorm(hs + res); res1 = hs + res
    norm_kernel<<<T_TOK, 256>>>(hs, res, opw, p_h1, p_res1, p_h1h, p_h1l);

    // 2) bcx = h1 @ in_proj^T (fp32 weights converted in-kernel)
    mma_gemm<0><<<dim3(3*D_HID/128, T_TOK/128, 1), 256, GEMM_SMEM>>>(
        p_h1h, p_h1l, inw, p_bcx, 3*D_HID, D_HID);

    // 3) short conv + C gate -> ypre hi/lo
    conv_kernel<<<(T_TOK*D_HID + 255)/256, 256>>>(convw);

    // 4) y = ypre @ out_proj^T
    mma_gemm<0><<<dim3(D_HID/128, T_TOK/128, 1), 256, GEMM_SMEM>>>(
        p_yph, p_ypl, outw, p_y, D_HID, D_HID);

    // 5) h2 = rmsnorm(y + res1); residual out
    norm_kernel<<<T_TOK, 256>>>(p_y, p_res1, ffnw, p_h2, res_out, p_h2h, p_h2l);

    // 6-9) gating + bucketing
    zero_counts_kernel<<<1, 32>>>();
    gate_kernel<<<T_TOK, NE*32>>>(p_h2, gw, gb);
    scan_kernel<<<1, 32>>>();
    fill_kernel<<<(TK + 255)/256, 256>>>();

    // 10) gu = gather(h2) @ w1[e]^T
    mma_gemm<1><<<dim3(2*FF/128, T_TOK/128, NE), 256, GEMM_SMEM>>>(
        p_h2h, p_h2l, w1, p_gu, 2*FF, D_HID);

    // 11) act = silu(g) * u  -> hi/lo
    act_kernel<<<(TK*FF + 255)/256, 256>>>();

    // 12) ye = act @ w2[e]^T; combine
    mma_gemm<2><<<dim3(D_HID/128, T_TOK/128, NE), 256, GEMM_SMEM>>>(
        p_acth, p_actl, w2, p_ye, D_HID, FF);
    combine_kernel<<<(T_TOK*D_HID + 255)/256, 256>>>(out);
}